// round 11
// baseline (speedup 1.0000x reference)
#include <cuda_runtime.h>
#include <cuda_fp16.h>
#include <cstdint>

// RNN_49684181680264 : Elman RNN forward, B=16384, T=1024, H=32.
//   h_t = tanh(h_{t-1} @ Whh + b_hh + x_t * Wxh + b_xh);  out = h_T @ Wout + b_out
//
// R11: R8/R9/R10 all pinned at ~560 cyc/warp-step regardless of structure;
// fitted model says MUFU.TANH f32 (16/tile-step, rt~16/SMSP) is the binder
// (~443 of 560 cyc). Fix: tanh in PACKED f16 -- cvt.rn.f16x2.f32 first (the
// instruction the repack already used), then tanh.approx.f16x2: 8 MUFU per
// tile-step instead of 16, and the tanh output IS the A fragment (pair
// (D[j][e],D[j][e+1]) <-> Ahi[kt][r] is a rename), so the repack stage
// disappears. Loop chain: HMMA -> FADD -> CVT -> MUFU.f16x2 -> HMMA.
// Keeps R10's 2-tiles-per-warp structure (512 CTAs x 1 warp).
// Precision: tanh input rounded to f16 (2^-11 class, same as measured-safe
// h-quant) + f16-grade tanh approx; expect rel_err 3-6e-4 < 1e-3.

#define RNN_T 1024
#define RNN_H 32
#define TILES 2
#define ROWS_PER_CTA (16 * TILES)
#define TT 32

typedef uint32_t u32;

__device__ __forceinline__ u32 pack_half2(float v0, float v1) {
    u32 d;
    asm("cvt.rn.f16x2.f32 %0, %1, %2;" : "=r"(d) : "f"(v1), "f"(v0));
    return d;
}
__device__ __forceinline__ void split_pair_init(float v0, float v1, u32 &hi, u32 &lo) {
    hi = pack_half2(v0, v1);
    __half2 h2 = *reinterpret_cast<const __half2*>(&hi);
    lo = pack_half2(v0 - __low2float(h2), v1 - __high2float(h2));
}
__device__ __forceinline__ void mma16816(float d[4], const u32 a[4], u32 b0, u32 b1) {
    asm volatile(
        "mma.sync.aligned.m16n8k16.row.col.f32.f16.f16.f32 "
        "{%0,%1,%2,%3}, {%4,%5,%6,%7}, {%8,%9}, {%0,%1,%2,%3};"
        : "+f"(d[0]), "+f"(d[1]), "+f"(d[2]), "+f"(d[3])
        : "r"(a[0]), "r"(a[1]), "r"(a[2]), "r"(a[3]), "r"(b0), "r"(b1));
}
__device__ __forceinline__ void mma16816_z(float d[4], const u32 a[4], u32 b0, u32 b1,
                                           float z) {
    asm volatile(
        "mma.sync.aligned.m16n8k16.row.col.f32.f16.f16.f32 "
        "{%0,%1,%2,%3}, {%4,%5,%6,%7}, {%8,%9}, {%10,%10,%10,%10};"
        : "=f"(d[0]), "=f"(d[1]), "=f"(d[2]), "=f"(d[3])
        : "r"(a[0]), "r"(a[1]), "r"(a[2]), "r"(a[3]), "r"(b0), "r"(b1),
          "f"(z));
}
// packed f16x2 tanh (sm_75+, no 'a' feature)
__device__ __forceinline__ u32 tanh_h2(u32 v) {
    u32 t;
    asm("tanh.approx.f16x2 %0, %1;" : "=r"(t) : "r"(v));
    return t;
}

__global__ __launch_bounds__(32)
void rnn_mma_kernel(const float* __restrict__ x,
                    const float* __restrict__ Wxh,
                    const float* __restrict__ b_xh,
                    const float* __restrict__ Whh,
                    const float* __restrict__ b_hh,
                    const float* __restrict__ Wout,
                    const float* __restrict__ b_out,
                    float* __restrict__ out)
{
    __shared__ float sX[ROWS_PER_CTA][TT + 1];

    const int lane = threadIdx.x;
    const int b0   = blockIdx.x * ROWS_PER_CTA;
    const int qr   = lane >> 2;
    const int qc   = (lane & 3) * 2;

    // ---- B fragments (register-resident, shared by both tiles) ----
    u32 Bhi[4][2][2], Blo[4][2][2];
    #pragma unroll
    for (int j = 0; j < 4; j++)
        #pragma unroll
        for (int kt = 0; kt < 2; kt++)
            #pragma unroll
            for (int r = 0; r < 2; r++) {
                int n = 8 * j + qr;
                int k = 16 * kt + 8 * r + qc;
                split_pair_init(Whh[k * RNN_H + n], Whh[(k + 1) * RNN_H + n],
                                Bhi[j][kt][r], Blo[j][kt][r]);
            }

    // ---- per-thread column constants ----
    float wxh[8], bs[8], wo[8];
    #pragma unroll
    for (int j = 0; j < 4; j++)
        #pragma unroll
        for (int e = 0; e < 2; e++) {
            int c = 8 * j + qc + e;
            wxh[2 * j + e] = Wxh[c];
            bs[2 * j + e]  = b_xh[c] + b_hh[c];
            wo[2 * j + e]  = Wout[c];
        }

    const float fz = 0.0f;

    // ---- A fragments per tile (h as f16), h = 0 ----
    // Layout closure: Ahi[u][kt][r] = tanh_f16x2 of D[j] pair, j=2kt+(r>>1),
    // pair=(r&1) -> elements (D[j][2*(r&1)], D[j][2*(r&1)+1]).
    u32 Ahi[TILES][2][4];
    #pragma unroll
    for (int u = 0; u < TILES; u++)
        #pragma unroll
        for (int kt = 0; kt < 2; kt++)
            #pragma unroll
            for (int r = 0; r < 4; r++) Ahi[u][kt][r] = 0u;

    for (int t0 = 0; t0 < RNN_T; t0 += TT) {
        __syncwarp();
        #pragma unroll
        for (int i = lane; i < ROWS_PER_CTA * TT; i += 32) {
            int r = i >> 5, c = i & 31;
            sX[r][c] = x[(size_t)(b0 + r) * RNN_T + t0 + c];
        }
        __syncwarp();

        #pragma unroll 1
        for (int tt = 0; tt < TT; tt++) {
            float DA[TILES][4][4], DB[TILES][4][4];

            // seeds for both tiles
            #pragma unroll
            for (int u = 0; u < TILES; u++) {
                float xv0 = sX[16 * u + qr][tt];
                float xv1 = sX[16 * u + qr + 8][tt];
                #pragma unroll
                for (int j = 0; j < 4; j++) {
                    DA[u][j][0] = fmaf(xv0, wxh[2 * j],     bs[2 * j]);
                    DA[u][j][1] = fmaf(xv0, wxh[2 * j + 1], bs[2 * j + 1]);
                    DA[u][j][2] = fmaf(xv1, wxh[2 * j],     bs[2 * j]);
                    DA[u][j][3] = fmaf(xv1, wxh[2 * j + 1], bs[2 * j + 1]);
                }
            }

            // MMAs: interleave the two tiles (independent chains)
            #pragma unroll
            for (int j = 0; j < 4; j++)
                #pragma unroll
                for (int u = 0; u < TILES; u++) {
                    mma16816  (DA[u][j], Ahi[u][0], Bhi[j][0][0], Bhi[j][0][1]);
                    mma16816_z(DB[u][j], Ahi[u][0], Blo[j][0][0], Blo[j][0][1], fz);
                    mma16816  (DA[u][j], Ahi[u][1], Bhi[j][1][0], Bhi[j][1][1]);
                    mma16816  (DB[u][j], Ahi[u][1], Blo[j][1][0], Blo[j][1][1]);
                }

            // h = tanh(D) in packed f16: pack pair -> tanh.f16x2 -> A fragment
            #pragma unroll
            for (int u = 0; u < TILES; u++)
                #pragma unroll
                for (int kt = 0; kt < 2; kt++)
                    #pragma unroll
                    for (int r = 0; r < 4; r++) {
                        int j = 2 * kt + (r >> 1);
                        int e = (r & 1) * 2;
                        u32 p = pack_half2(DA[u][j][e]     + DB[u][j][e],
                                           DA[u][j][e + 1] + DB[u][j][e + 1]);
                        Ahi[u][kt][r] = tanh_h2(p);
                    }
        }
    }

    // ---- epilogue: out[b] = h . Wout + b_out, per tile ----
    #pragma unroll
    for (int u = 0; u < TILES; u++) {
        float po0 = 0.0f, po1 = 0.0f;
        #pragma unroll
        for (int kt = 0; kt < 2; kt++)
            #pragma unroll
            for (int r = 0; r < 4; r++) {
                int j = 2 * kt + (r >> 1);
                int e = (r & 1) * 2;
                __half2 h2 = *reinterpret_cast<const __half2*>(&Ahi[u][kt][r]);
                float v0 = __low2float(h2);
                float v1 = __high2float(h2);
                if (e == 0) {   // rows qr (elements 0,1)
                    po0 = fmaf(v0, wo[2 * j],     po0);
                    po0 = fmaf(v1, wo[2 * j + 1], po0);
                } else {        // rows qr+8 (elements 2,3)
                    po1 = fmaf(v0, wo[2 * j],     po1);
                    po1 = fmaf(v1, wo[2 * j + 1], po1);
                }
            }
        po0 += __shfl_xor_sync(0xFFFFFFFFu, po0, 1);
        po0 += __shfl_xor_sync(0xFFFFFFFFu, po0, 2);
        po1 += __shfl_xor_sync(0xFFFFFFFFu, po1, 1);
        po1 += __shfl_xor_sync(0xFFFFFFFFu, po1, 2);
        if ((lane & 3) == 0) {
            float bo = b_out[0];
            out[b0 + 16 * u + qr]     = po0 + bo;
            out[b0 + 16 * u + qr + 8] = po1 + bo;
        }
    }
}

extern "C" void kernel_launch(void* const* d_in, const int* in_sizes, int n_in,
                              void* d_out, int out_size)
{
    const float* x     = (const float*)d_in[0];
    const float* Wxh   = (const float*)d_in[1];
    const float* b_xh  = (const float*)d_in[2];
    const float* Whh   = (const float*)d_in[3];
    const float* b_hh  = (const float*)d_in[4];
    const float* Wout  = (const float*)d_in[5];
    const float* b_out = (const float*)d_in[6];
    float* out = (float*)d_out;

    dim3 grid(16384 / ROWS_PER_CTA);   // 512 CTAs, one warp, two tiles each
    dim3 blk(32);
    rnn_mma_kernel<<<grid, blk>>>(x, Wxh, b_xh, Whh, b_hh, Wout, b_out, out);
}

// round 12
// speedup vs baseline: 1.1445x; 1.1445x over previous
#include <cuda_runtime.h>
#include <cuda_fp16.h>
#include <cstdint>

// RNN_49684181680264 : Elman RNN forward, B=16384, T=1024, H=32.
//   h_t = tanh(h_{t-1} @ Whh + b_hh + x_t * Wxh + b_xh);  out = h_T @ Wout + b_out
//
// R12: R8-R11 showed the wall (~560 cyc/warp-step) is the serial recurrence's
// per-step execution time; the only lever that moved it was cutting step-body
// instructions (R7->R8). This round: W quantized to f16 round-to-nearest
// (single B fragment set, no lo-pass) -> 8 HMMA/tile-step in two 2-deep
// chains; f32 MUFU.TANH and direct CVT repack kept (R11 proved the f16-tanh
// variant slower AND less accurate). 48 instr/tile-step vs 72.
// Precision: W-quant ~2^-12-rel systematic; measured contractivity (R7, R8)
// predicts final rel_err 3.5-6e-4 < 1e-3. Revert path = R10 (258us, 2.6e-4).

#define RNN_T 1024
#define RNN_H 32
#define TILES 2
#define ROWS_PER_CTA (16 * TILES)
#define TT 32

typedef uint32_t u32;

__device__ __forceinline__ u32 pack_half2(float v0, float v1) {
    u32 d;
    asm("cvt.rn.f16x2.f32 %0, %1, %2;" : "=r"(d) : "f"(v1), "f"(v0));
    return d;
}
__device__ __forceinline__ void mma16816(float d[4], const u32 a[4], u32 b0, u32 b1) {
    asm volatile(
        "mma.sync.aligned.m16n8k16.row.col.f32.f16.f16.f32 "
        "{%0,%1,%2,%3}, {%4,%5,%6,%7}, {%8,%9}, {%0,%1,%2,%3};"
        : "+f"(d[0]), "+f"(d[1]), "+f"(d[2]), "+f"(d[3])
        : "r"(a[0]), "r"(a[1]), "r"(a[2]), "r"(a[3]), "r"(b0), "r"(b1));
}
__device__ __forceinline__ float tanh_mufu(float v) {
    float t;
    asm("tanh.approx.f32 %0, %1;" : "=f"(t) : "f"(v));
    return t;
}

__global__ __launch_bounds__(32)
void rnn_mma_kernel(const float* __restrict__ x,
                    const float* __restrict__ Wxh,
                    const float* __restrict__ b_xh,
                    const float* __restrict__ Whh,
                    const float* __restrict__ b_hh,
                    const float* __restrict__ Wout,
                    const float* __restrict__ b_out,
                    float* __restrict__ out)
{
    __shared__ float sX[ROWS_PER_CTA][TT + 1];

    const int lane = threadIdx.x;
    const int b0   = blockIdx.x * ROWS_PER_CTA;
    const int qr   = lane >> 2;
    const int qc   = (lane & 3) * 2;

    // ---- B fragments: W as round-to-nearest f16, register-resident ----
    u32 Bh[4][2][2];
    #pragma unroll
    for (int j = 0; j < 4; j++)
        #pragma unroll
        for (int kt = 0; kt < 2; kt++)
            #pragma unroll
            for (int r = 0; r < 2; r++) {
                int n = 8 * j + qr;
                int k = 16 * kt + 8 * r + qc;
                Bh[j][kt][r] = pack_half2(Whh[k * RNN_H + n],
                                          Whh[(k + 1) * RNN_H + n]);
            }

    // ---- per-thread column constants ----
    float wxh[8], bs[8], wo[8];
    #pragma unroll
    for (int j = 0; j < 4; j++)
        #pragma unroll
        for (int e = 0; e < 2; e++) {
            int c = 8 * j + qc + e;
            wxh[2 * j + e] = Wxh[c];
            bs[2 * j + e]  = b_xh[c] + b_hh[c];
            wo[2 * j + e]  = Wout[c];
        }

    // ---- A fragments per tile (h as f16), h = 0 ----
    u32 Ahi[TILES][2][4];
    #pragma unroll
    for (int u = 0; u < TILES; u++)
        #pragma unroll
        for (int kt = 0; kt < 2; kt++)
            #pragma unroll
            for (int r = 0; r < 4; r++) Ahi[u][kt][r] = 0u;

    float th[TILES][16];

    for (int t0 = 0; t0 < RNN_T; t0 += TT) {
        __syncwarp();
        #pragma unroll
        for (int i = lane; i < ROWS_PER_CTA * TT; i += 32) {
            int r = i >> 5, c = i & 31;
            sX[r][c] = x[(size_t)(b0 + r) * RNN_T + t0 + c];
        }
        __syncwarp();

        #pragma unroll 1
        for (int tt = 0; tt < TT; tt++) {
            float D[TILES][4][4];

            // seeds for both tiles: D = bias + x*Wxh
            #pragma unroll
            for (int u = 0; u < TILES; u++) {
                float xv0 = sX[16 * u + qr][tt];
                float xv1 = sX[16 * u + qr + 8][tt];
                #pragma unroll
                for (int j = 0; j < 4; j++) {
                    D[u][j][0] = fmaf(xv0, wxh[2 * j],     bs[2 * j]);
                    D[u][j][1] = fmaf(xv0, wxh[2 * j + 1], bs[2 * j + 1]);
                    D[u][j][2] = fmaf(xv1, wxh[2 * j],     bs[2 * j]);
                    D[u][j][3] = fmaf(xv1, wxh[2 * j + 1], bs[2 * j + 1]);
                }
            }

            // 8 HMMA per tile: 4 n-tiles x 2-deep kt chain (tiles interleaved)
            #pragma unroll
            for (int j = 0; j < 4; j++)
                #pragma unroll
                for (int u = 0; u < TILES; u++) {
                    mma16816(D[u][j], Ahi[u][0], Bh[j][0][0], Bh[j][0][1]);
                    mma16816(D[u][j], Ahi[u][1], Bh[j][1][0], Bh[j][1][1]);
                }

            // h = tanh(D), f32 MUFU; repack to A fragments (layout closure)
            #pragma unroll
            for (int u = 0; u < TILES; u++) {
                #pragma unroll
                for (int j = 0; j < 4; j++) {
                    th[u][4 * j]     = tanh_mufu(D[u][j][0]);
                    th[u][4 * j + 1] = tanh_mufu(D[u][j][1]);
                    th[u][4 * j + 2] = tanh_mufu(D[u][j][2]);
                    th[u][4 * j + 3] = tanh_mufu(D[u][j][3]);
                }
                #pragma unroll
                for (int kt = 0; kt < 2; kt++)
                    #pragma unroll
                    for (int r = 0; r < 4; r++) {
                        int j = 2 * kt + (r >> 1);
                        int e = (r & 1) * 2;
                        Ahi[u][kt][r] = pack_half2(th[u][4 * j + e],
                                                   th[u][4 * j + e + 1]);
                    }
            }
        }
    }

    // ---- epilogue: out[b] = h . Wout + b_out, per tile ----
    #pragma unroll
    for (int u = 0; u < TILES; u++) {
        float po0 = 0.0f, po1 = 0.0f;
        #pragma unroll
        for (int j = 0; j < 4; j++) {
            po0 = fmaf(th[u][4 * j],     wo[2 * j],     po0);
            po0 = fmaf(th[u][4 * j + 1], wo[2 * j + 1], po0);
            po1 = fmaf(th[u][4 * j + 2], wo[2 * j],     po1);
            po1 = fmaf(th[u][4 * j + 3], wo[2 * j + 1], po1);
        }
        po0 += __shfl_xor_sync(0xFFFFFFFFu, po0, 1);
        po0 += __shfl_xor_sync(0xFFFFFFFFu, po0, 2);
        po1 += __shfl_xor_sync(0xFFFFFFFFu, po1, 1);
        po1 += __shfl_xor_sync(0xFFFFFFFFu, po1, 2);
        if ((lane & 3) == 0) {
            float bo = b_out[0];
            out[b0 + 16 * u + qr]     = po0 + bo;
            out[b0 + 16 * u + qr + 8] = po1 + bo;
        }
    }
}

extern "C" void kernel_launch(void* const* d_in, const int* in_sizes, int n_in,
                              void* d_out, int out_size)
{
    const float* x     = (const float*)d_in[0];
    const float* Wxh   = (const float*)d_in[1];
    const float* b_xh  = (const float*)d_in[2];
    const float* Whh   = (const float*)d_in[3];
    const float* b_hh  = (const float*)d_in[4];
    const float* Wout  = (const float*)d_in[5];
    const float* b_out = (const float*)d_in[6];
    float* out = (float*)d_out;

    dim3 grid(16384 / ROWS_PER_CTA);   // 512 CTAs, one warp, two tiles each
    dim3 blk(32);
    rnn_mma_kernel<<<grid, blk>>>(x, Wxh, b_xh, Whh, b_hh, Wout, b_out, out);
}